// round 11
// baseline (speedup 1.0000x reference)
#include <cuda_runtime.h>
#include <cstdint>

#define T_DIM 2048
#define B_DIM 4
#define E_DIM 512
#define H_DIM 8
#define HD 64
#define M0 8192        // T*B
#define N_QKV 1536     // 3*E
#define ROWSTRIDE 6144 // B_DIM * N_QKV: float stride between consecutive t (fixed b) in g_qkv
#define SSTRIDE 132    // smem row stride for 128-wide k-major operand tiles
#define PSTRIDE 68     // smem row stride for 64-wide tiles (av P and V)

// ---- scratch (static device globals; ~192 MB — proven-safe footprint) ----
__device__ float  g_qkv[(size_t)M0 * N_QKV];                   // 48 MB  [t*B+b, 3E]
__device__ float  g_sc[(size_t)H_DIM * T_DIM * T_DIM];         // 128 MB [h, T, T] raw scores, one batch-group
__device__ float  g_attn[(size_t)M0 * E_DIM];                  // 16 MB  [t*B+b, E]
__device__ float2 g_stats[H_DIM * T_DIM];                      // 128 KB (rowmax, 1/rowsum) per (h,i)

// ============================================================================
// tf32 helpers
// ============================================================================
__device__ __forceinline__ uint32_t f2tf(float f) {
    uint32_t u;
    asm("cvt.rna.tf32.f32 %0, %1;" : "=r"(u) : "f"(f));
    return u;
}

__device__ __forceinline__ void mma8(float* c, const uint32_t* a, const uint32_t* b) {
    asm volatile(
        "mma.sync.aligned.m16n8k8.row.col.f32.tf32.tf32.f32 "
        "{%0,%1,%2,%3}, {%4,%5,%6,%7}, {%8,%9}, {%0,%1,%2,%3};\n"
        : "+f"(c[0]), "+f"(c[1]), "+f"(c[2]), "+f"(c[3])
        : "r"(a[0]), "r"(a[1]), "r"(a[2]), "r"(a[3]), "r"(b[0]), "r"(b[1]));
}

// Stage one float4 of a k-contiguous gmem tile into k-major smem (S[k][row]).
__device__ __forceinline__ void stage_frag(const float* __restrict__ src, size_t rstride,
                                           uint32_t* S, int p) {
    int r = p >> 3;
    int c4 = (p & 7) << 2;
    float4 v = *reinterpret_cast<const float4*>(src + (size_t)r * rstride + c4);
    S[(c4 + 0) * SSTRIDE + r] = f2tf(v.x);
    S[(c4 + 1) * SSTRIDE + r] = f2tf(v.y);
    S[(c4 + 2) * SSTRIDE + r] = f2tf(v.z);
    S[(c4 + 3) * SSTRIDE + r] = f2tf(v.w);
}

// Warp-level (MT*16) x 32 output tile over one staged Ktile=32.
template <int MT, int ASTRIDE, int BSTRIDE>
__device__ __forceinline__ void warp_mma(const uint32_t* __restrict__ A,
                                         const uint32_t* __restrict__ B,
                                         int m0, int n0, int gid, int tig,
                                         float acc[MT][4][4]) {
    #pragma unroll
    for (int ks = 0; ks < 4; ++ks) {
        const int k = ks * 8;
        uint32_t a[MT][4], b[4][2];
        #pragma unroll
        for (int mt = 0; mt < MT; ++mt) {
            int m = m0 + mt * 16 + gid;
            a[mt][0] = A[(k + tig) * ASTRIDE + m];
            a[mt][1] = A[(k + tig) * ASTRIDE + m + 8];
            a[mt][2] = A[(k + tig + 4) * ASTRIDE + m];
            a[mt][3] = A[(k + tig + 4) * ASTRIDE + m + 8];
        }
        #pragma unroll
        for (int nt = 0; nt < 4; ++nt) {
            int n = n0 + nt * 8 + gid;
            b[nt][0] = B[(k + tig) * BSTRIDE + n];
            b[nt][1] = B[(k + tig + 4) * BSTRIDE + n];
        }
        #pragma unroll
        for (int mt = 0; mt < MT; ++mt)
            #pragma unroll
            for (int nt = 0; nt < 4; ++nt)
                mma8(acc[mt][nt], a[mt], b[nt]);
    }
}

// ============================================================================
// Projection GEMM: C[M,N] = A[M,K] @ W[N,K]^T + bias (tf32). Block 128x128,
// 256 threads (8 warps 2m x 4n, warp tile 64x32), Ktile 32.
// ============================================================================
__device__ __forceinline__ void gemm_tf32_body(
    const float* __restrict__ A, const float* __restrict__ W,
    const float* __restrict__ bias, float* __restrict__ C,
    int N, int K, int scaleCols, float scaleVal)
{
    __shared__ uint32_t As[32 * SSTRIDE];
    __shared__ uint32_t Bs[32 * SSTRIDE];
    const int tid = threadIdx.x;
    const int lane = tid & 31;
    const int gid = lane >> 2, tig = lane & 3;
    const int warp = tid >> 5;
    const int m0w = (warp >> 2) * 64, n0w = (warp & 3) * 32;
    const int mBase = blockIdx.y * 128, nBase = blockIdx.x * 128;

    float acc[4][4][4] = {};

    for (int k0 = 0; k0 < K; k0 += 32) {
        #pragma unroll
        for (int l = 0; l < 4; ++l) {
            stage_frag(A + (size_t)mBase * K + k0, K, As, tid + l * 256);
            stage_frag(W + (size_t)nBase * K + k0, K, Bs, tid + l * 256);
        }
        __syncthreads();
        warp_mma<4, SSTRIDE, SSTRIDE>(As, Bs, m0w, n0w, gid, tig, acc);
        __syncthreads();
    }

    #pragma unroll
    for (int mt = 0; mt < 4; ++mt) {
        int r0 = mBase + m0w + mt * 16 + gid;
        #pragma unroll
        for (int nt = 0; nt < 4; ++nt) {
            int c = nBase + n0w + nt * 8 + tig * 2;
            float b0 = bias[c], b1 = bias[c + 1];
            float2 v0 = make_float2(acc[mt][nt][0] + b0, acc[mt][nt][1] + b1);
            float2 v1 = make_float2(acc[mt][nt][2] + b0, acc[mt][nt][3] + b1);
            if (c < scaleCols) { v0.x *= scaleVal; v0.y *= scaleVal; v1.x *= scaleVal; v1.y *= scaleVal; }
            *reinterpret_cast<float2*>(C + (size_t)r0 * N + c) = v0;
            *reinterpret_cast<float2*>(C + (size_t)(r0 + 8) * N + c) = v1;
        }
    }
}

__global__ __launch_bounds__(256) void qkv_kernel(
    const float* __restrict__ x, const float* __restrict__ w_in,
    const float* __restrict__ b_in)
{
    gemm_tf32_body(x, w_in, b_in, &g_qkv[0], N_QKV, E_DIM, E_DIM, 0.125f);
}

__global__ __launch_bounds__(256) void outproj_kernel(
    const float* __restrict__ w_out, const float* __restrict__ b_out,
    float* __restrict__ out_attn)
{
    gemm_tf32_body(&g_attn[0], w_out, b_out, out_attn, E_DIM, E_DIM, 0, 1.0f);
}

// ============================================================================
// Scores (raw, q pre-scaled) for batch-group b, head h=blockIdx.z.
// Block 128x128, 256 thr. Grid (16,16,8).
// ============================================================================
__global__ __launch_bounds__(256) void scores_kernel(int b)
{
    __shared__ uint32_t Qs[32 * SSTRIDE];
    __shared__ uint32_t Ks[32 * SSTRIDE];
    const int tid = threadIdx.x;
    const int lane = tid & 31;
    const int gid = lane >> 2, tig = lane & 3;
    const int warp = tid >> 5;
    const int m0w = (warp >> 2) * 64, n0w = (warp & 3) * 32;
    const int h = blockIdx.z;
    const int iBase = blockIdx.y * 128, jBase = blockIdx.x * 128;
    const float* Qb = &g_qkv[0] + b * N_QKV + h * HD + (size_t)iBase * ROWSTRIDE;
    const float* Kb = &g_qkv[0] + b * N_QKV + E_DIM + h * HD + (size_t)jBase * ROWSTRIDE;

    float acc[4][4][4] = {};

    #pragma unroll
    for (int k0 = 0; k0 < HD; k0 += 32) {
        #pragma unroll
        for (int l = 0; l < 4; ++l) {
            stage_frag(Qb + k0, ROWSTRIDE, Qs, tid + l * 256);
            stage_frag(Kb + k0, ROWSTRIDE, Ks, tid + l * 256);
        }
        __syncthreads();
        warp_mma<4, SSTRIDE, SSTRIDE>(Qs, Ks, m0w, n0w, gid, tig, acc);
        __syncthreads();
    }

    float* S = &g_sc[0] + (size_t)h * T_DIM * T_DIM;
    #pragma unroll
    for (int mt = 0; mt < 4; ++mt) {
        int r0 = iBase + m0w + mt * 16 + gid;
        #pragma unroll
        for (int nt = 0; nt < 4; ++nt) {
            int c = jBase + n0w + nt * 8 + tig * 2;
            *reinterpret_cast<float2*>(S + (size_t)r0 * T_DIM + c) =
                make_float2(acc[mt][nt][0], acc[mt][nt][1]);
            *reinterpret_cast<float2*>(S + (size_t)(r0 + 8) * T_DIM + c) =
                make_float2(acc[mt][nt][2], acc[mt][nt][3]);
        }
    }
}

// ============================================================================
// Row stats + head-average for batch-group b. One block per row i.
// Reads RAW scores once; writes (max, 1/sum) to g_stats and the averaged
// probabilities to out_avg. No probability writeback. Grid (2048).
// ============================================================================
__global__ __launch_bounds__(256) void rowstats_avg_kernel(int b, float* __restrict__ out_avg)
{
    __shared__ float sm[8];
    const int tid = threadIdx.x;
    const int i = blockIdx.x;

    float accum[8] = {};

    for (int h = 0; h < H_DIM; ++h) {
        const float* p = &g_sc[0] + ((size_t)h * T_DIM + i) * T_DIM;

        float r[8];
        #pragma unroll
        for (int j = 0; j < 8; ++j) r[j] = p[tid + j * 256];

        float m = r[0];
        #pragma unroll
        for (int j = 1; j < 8; ++j) m = fmaxf(m, r[j]);
        #pragma unroll
        for (int o = 16; o > 0; o >>= 1) m = fmaxf(m, __shfl_xor_sync(0xffffffffu, m, o));
        if ((tid & 31) == 0) sm[tid >> 5] = m;
        __syncthreads();
        m = sm[0];
        #pragma unroll
        for (int w = 1; w < 8; ++w) m = fmaxf(m, sm[w]);
        __syncthreads();

        float s = 0.f;
        #pragma unroll
        for (int j = 0; j < 8; ++j) { r[j] = __expf(r[j] - m); s += r[j]; }
        #pragma unroll
        for (int o = 16; o > 0; o >>= 1) s += __shfl_xor_sync(0xffffffffu, s, o);
        if ((tid & 31) == 0) sm[tid >> 5] = s;
        __syncthreads();
        s = 0.f;
        #pragma unroll
        for (int w = 0; w < 8; ++w) s += sm[w];

        float inv = 1.0f / s;
        if (tid == 0) g_stats[h * T_DIM + i] = make_float2(m, inv);
        #pragma unroll
        for (int j = 0; j < 8; ++j) accum[j] += r[j] * inv;
        __syncthreads();
    }

    float* q = out_avg + ((size_t)b * T_DIM + i) * T_DIM;
    #pragma unroll
    for (int j = 0; j < 8; ++j) q[tid + j * 256] = accum[j] * 0.125f;
}

// ============================================================================
// AV for batch-group b, head h=blockIdx.y: C = softmax(S) @ V, softmax applied
// on the fly from g_stats during staging.
// Block 64m x 64n, 128 threads (4 warps 2m x 2n, warp tile 32x32), Ktile 32.
// Register-prefetch, smem 17.9 KB -> multiple CTAs/SM (occupancy fix: R9/R10
// ran 1 CTA/SM at occ 12.5%). Grid (32, 8) = 256 blocks.
// ============================================================================
__global__ __launch_bounds__(128) void av_kernel(int b)
{
    __shared__ uint32_t Ps[32 * PSTRIDE];   // 8.7 KB  [k][row], 64 rows
    __shared__ uint32_t Vs[32 * PSTRIDE];   // 8.7 KB  [k][n],  64 cols
    __shared__ float2 sst[64];              // 0.5 KB

    const int tid = threadIdx.x;
    const int lane = tid & 31;
    const int gid = lane >> 2, tig = lane & 3;
    const int warp = tid >> 5;
    const int m0w = (warp >> 1) * 32, n0w = (warp & 1) * 32;
    const int h = blockIdx.y;
    const int iBase = blockIdx.x * 64;
    const float* Pm = &g_sc[0] + (size_t)h * T_DIM * T_DIM + (size_t)iBase * T_DIM;
    const float* Vb = &g_qkv[0] + b * N_QKV + 2 * E_DIM + h * HD;

    if (tid < 64) sst[tid] = g_stats[h * T_DIM + iBase + tid];
    __syncthreads();

    float acc[2][4][4] = {};
    float4 pv[4], vv[4];

    // ---- issue LDGs for k-tile k0 into registers ----
    auto load_tiles = [&](int k0) {
        #pragma unroll
        for (int l = 0; l < 4; ++l) {
            int p = tid + l * 128;               // 64 rows x 8 float4-chunks
            int r = p >> 3, c4 = (p & 7) << 2;
            pv[l] = *reinterpret_cast<const float4*>(Pm + (size_t)r * T_DIM + k0 + c4);
        }
        #pragma unroll
        for (int l = 0; l < 4; ++l) {
            int p = tid + l * 128;               // 32 k x 16 float4-chunks
            int k = p >> 4, n4 = (p & 15) << 2;
            vv[l] = *reinterpret_cast<const float4*>(Vb + (size_t)(k0 + k) * ROWSTRIDE + n4);
        }
    };

    // ---- exp-normalize / convert + store registers into smem ----
    auto store_tiles = [&]() {
        #pragma unroll
        for (int l = 0; l < 4; ++l) {
            int p = tid + l * 128;
            int r = p >> 3, c4 = (p & 7) << 2;
            float2 st = sst[r];                  // x = rowmax, y = 1/rowsum
            float4 v = pv[l];
            Ps[(c4 + 0) * PSTRIDE + r] = f2tf(__expf(v.x - st.x) * st.y);
            Ps[(c4 + 1) * PSTRIDE + r] = f2tf(__expf(v.y - st.x) * st.y);
            Ps[(c4 + 2) * PSTRIDE + r] = f2tf(__expf(v.z - st.x) * st.y);
            Ps[(c4 + 3) * PSTRIDE + r] = f2tf(__expf(v.w - st.x) * st.y);
        }
        #pragma unroll
        for (int l = 0; l < 4; ++l) {
            int p = tid + l * 128;
            int k = p >> 4, n4 = (p & 15) << 2;
            float4 v = vv[l];
            Vs[k * PSTRIDE + n4 + 0] = f2tf(v.x);
            Vs[k * PSTRIDE + n4 + 1] = f2tf(v.y);
            Vs[k * PSTRIDE + n4 + 2] = f2tf(v.z);
            Vs[k * PSTRIDE + n4 + 3] = f2tf(v.w);
        }
    };

    load_tiles(0);
    store_tiles();
    __syncthreads();

    const int NT = T_DIM / 32;   // 64 k-tiles
    for (int t = 0; t < NT; ++t) {
        if (t + 1 < NT) load_tiles((t + 1) * 32);   // LDGs in flight during mma
        warp_mma<2, PSTRIDE, PSTRIDE>(Ps, Vs, m0w, n0w, gid, tig, acc);
        __syncthreads();
        if (t + 1 < NT) {
            store_tiles();
            __syncthreads();
        }
    }

    #pragma unroll
    for (int mt = 0; mt < 2; ++mt) {
        int i0 = iBase + m0w + mt * 16 + gid;
        #pragma unroll
        for (int nt = 0; nt < 4; ++nt) {
            int n = n0w + nt * 8 + tig * 2;
            *reinterpret_cast<float2*>(&g_attn[((size_t)i0 * B_DIM + b) * E_DIM + h * HD + n]) =
                make_float2(acc[mt][nt][0], acc[mt][nt][1]);
            *reinterpret_cast<float2*>(&g_attn[((size_t)(i0 + 8) * B_DIM + b) * E_DIM + h * HD + n]) =
                make_float2(acc[mt][nt][2], acc[mt][nt][3]);
        }
    }
}

// ============================================================================
// Host launch — kernel launches only (graph-capturable)
// ============================================================================
extern "C" void kernel_launch(void* const* d_in, const int* in_sizes, int n_in,
                              void* d_out, int out_size)
{
    const float* x     = (const float*)d_in[0];  // [T,B,E]
    const float* w_in  = (const float*)d_in[1];  // [3E,E]
    const float* b_in  = (const float*)d_in[2];  // [3E]
    const float* w_out = (const float*)d_in[3];  // [E,E]
    const float* b_out = (const float*)d_in[4];  // [E]

    float* out_attn = (float*)d_out;                        // [T,B,E]
    float* out_avg  = out_attn + (size_t)M0 * E_DIM;        // [B,T,T]

    // 1) QKV projection (+bias, q scaled by HD^-0.5)
    qkv_kernel<<<dim3(N_QKV / 128, M0 / 128), 256>>>(x, w_in, b_in);

    // 2) per batch-group: raw scores -> row stats + avg -> AV (softmax fused)
    for (int b = 0; b < B_DIM; ++b) {
        scores_kernel<<<dim3(T_DIM / 128, T_DIM / 128, H_DIM), 256>>>(b);
        rowstats_avg_kernel<<<dim3(T_DIM), 256>>>(b, out_avg);
        av_kernel<<<dim3(T_DIM / 64, H_DIM), 128>>>(b);
    }

    // 3) out projection (+bias) -> first output
    outproj_kernel<<<dim3(E_DIM / 128, M0 / 128), 256>>>(w_out, b_out, out_attn);
}

// round 13
// speedup vs baseline: 1.0494x; 1.0494x over previous
#include <cuda_runtime.h>
#include <cstdint>

#define T_DIM 2048
#define B_DIM 4
#define E_DIM 512
#define H_DIM 8
#define HD 64
#define M0 8192        // T*B
#define N_QKV 1536     // 3*E
#define ROWSTRIDE 6144 // B_DIM * N_QKV: float stride between consecutive t (fixed b) in g_qkv
#define SSTRIDE 132    // smem row stride for 128-wide k-major operand tiles
#define PSTRIDE 68     // smem row stride for 64-wide tiles (av P and V)
#define NSPLIT 4       // av split-K factor
#define KSPLIT 512     // k-range per av split (T_DIM / NSPLIT)

// ---- scratch (static device globals; ~208 MB) ----
__device__ float  g_qkv[(size_t)M0 * N_QKV];                   // 48 MB  [t*B+b, 3E]
__device__ float  g_sc[(size_t)H_DIM * T_DIM * T_DIM];         // 128 MB [h, T, T] raw scores, one batch-group
__device__ float  g_attn[(size_t)M0 * E_DIM];                  // 16 MB  [t*B+b, E]
__device__ float  g_part[NSPLIT][(size_t)T_DIM * E_DIM];       // 16 MB  split-K partials, one batch-group
__device__ float2 g_stats[H_DIM * T_DIM];                      // 128 KB (rowmax, 1/rowsum) per (h,i)

// ============================================================================
// tf32 helpers
// ============================================================================
__device__ __forceinline__ uint32_t f2tf(float f) {
    uint32_t u;
    asm("cvt.rna.tf32.f32 %0, %1;" : "=r"(u) : "f"(f));
    return u;
}

__device__ __forceinline__ void mma8(float* c, const uint32_t* a, const uint32_t* b) {
    asm volatile(
        "mma.sync.aligned.m16n8k8.row.col.f32.tf32.tf32.f32 "
        "{%0,%1,%2,%3}, {%4,%5,%6,%7}, {%8,%9}, {%0,%1,%2,%3};\n"
        : "+f"(c[0]), "+f"(c[1]), "+f"(c[2]), "+f"(c[3])
        : "r"(a[0]), "r"(a[1]), "r"(a[2]), "r"(a[3]), "r"(b[0]), "r"(b[1]));
}

// Stage one float4 of a k-contiguous gmem tile into k-major smem (S[k][row]).
__device__ __forceinline__ void stage_frag(const float* __restrict__ src, size_t rstride,
                                           uint32_t* S, int p) {
    int r = p >> 3;
    int c4 = (p & 7) << 2;
    float4 v = *reinterpret_cast<const float4*>(src + (size_t)r * rstride + c4);
    S[(c4 + 0) * SSTRIDE + r] = f2tf(v.x);
    S[(c4 + 1) * SSTRIDE + r] = f2tf(v.y);
    S[(c4 + 2) * SSTRIDE + r] = f2tf(v.z);
    S[(c4 + 3) * SSTRIDE + r] = f2tf(v.w);
}

// Warp-level (MT*16) x 32 output tile over one staged Ktile=32.
template <int MT, int ASTRIDE, int BSTRIDE>
__device__ __forceinline__ void warp_mma(const uint32_t* __restrict__ A,
                                         const uint32_t* __restrict__ B,
                                         int m0, int n0, int gid, int tig,
                                         float acc[MT][4][4]) {
    #pragma unroll
    for (int ks = 0; ks < 4; ++ks) {
        const int k = ks * 8;
        uint32_t a[MT][4], b[4][2];
        #pragma unroll
        for (int mt = 0; mt < MT; ++mt) {
            int m = m0 + mt * 16 + gid;
            a[mt][0] = A[(k + tig) * ASTRIDE + m];
            a[mt][1] = A[(k + tig) * ASTRIDE + m + 8];
            a[mt][2] = A[(k + tig + 4) * ASTRIDE + m];
            a[mt][3] = A[(k + tig + 4) * ASTRIDE + m + 8];
        }
        #pragma unroll
        for (int nt = 0; nt < 4; ++nt) {
            int n = n0 + nt * 8 + gid;
            b[nt][0] = B[(k + tig) * BSTRIDE + n];
            b[nt][1] = B[(k + tig + 4) * BSTRIDE + n];
        }
        #pragma unroll
        for (int mt = 0; mt < MT; ++mt)
            #pragma unroll
            for (int nt = 0; nt < 4; ++nt)
                mma8(acc[mt][nt], a[mt], b[nt]);
    }
}

// ============================================================================
// Projection GEMM: C[M,N] = A[M,K] @ W[N,K]^T + bias (tf32). Block 128x128,
// 256 threads (8 warps 2m x 4n, warp tile 64x32), Ktile 32.
// ============================================================================
__device__ __forceinline__ void gemm_tf32_body(
    const float* __restrict__ A, const float* __restrict__ W,
    const float* __restrict__ bias, float* __restrict__ C,
    int N, int K, int scaleCols, float scaleVal)
{
    __shared__ uint32_t As[32 * SSTRIDE];
    __shared__ uint32_t Bs[32 * SSTRIDE];
    const int tid = threadIdx.x;
    const int lane = tid & 31;
    const int gid = lane >> 2, tig = lane & 3;
    const int warp = tid >> 5;
    const int m0w = (warp >> 2) * 64, n0w = (warp & 3) * 32;
    const int mBase = blockIdx.y * 128, nBase = blockIdx.x * 128;

    float acc[4][4][4] = {};

    for (int k0 = 0; k0 < K; k0 += 32) {
        #pragma unroll
        for (int l = 0; l < 4; ++l) {
            stage_frag(A + (size_t)mBase * K + k0, K, As, tid + l * 256);
            stage_frag(W + (size_t)nBase * K + k0, K, Bs, tid + l * 256);
        }
        __syncthreads();
        warp_mma<4, SSTRIDE, SSTRIDE>(As, Bs, m0w, n0w, gid, tig, acc);
        __syncthreads();
    }

    #pragma unroll
    for (int mt = 0; mt < 4; ++mt) {
        int r0 = mBase + m0w + mt * 16 + gid;
        #pragma unroll
        for (int nt = 0; nt < 4; ++nt) {
            int c = nBase + n0w + nt * 8 + tig * 2;
            float b0 = bias[c], b1 = bias[c + 1];
            float2 v0 = make_float2(acc[mt][nt][0] + b0, acc[mt][nt][1] + b1);
            float2 v1 = make_float2(acc[mt][nt][2] + b0, acc[mt][nt][3] + b1);
            if (c < scaleCols) { v0.x *= scaleVal; v0.y *= scaleVal; v1.x *= scaleVal; v1.y *= scaleVal; }
            *reinterpret_cast<float2*>(C + (size_t)r0 * N + c) = v0;
            *reinterpret_cast<float2*>(C + (size_t)(r0 + 8) * N + c) = v1;
        }
    }
}

__global__ __launch_bounds__(256) void qkv_kernel(
    const float* __restrict__ x, const float* __restrict__ w_in,
    const float* __restrict__ b_in)
{
    gemm_tf32_body(x, w_in, b_in, &g_qkv[0], N_QKV, E_DIM, E_DIM, 0.125f);
}

__global__ __launch_bounds__(256) void outproj_kernel(
    const float* __restrict__ w_out, const float* __restrict__ b_out,
    float* __restrict__ out_attn)
{
    gemm_tf32_body(&g_attn[0], w_out, b_out, out_attn, E_DIM, E_DIM, 0, 1.0f);
}

// ============================================================================
// Scores (raw, q pre-scaled) for batch-group b, head h=blockIdx.z.
// Block 128x128, 256 thr. Grid (16,16,8).
// ============================================================================
__global__ __launch_bounds__(256) void scores_kernel(int b)
{
    __shared__ uint32_t Qs[32 * SSTRIDE];
    __shared__ uint32_t Ks[32 * SSTRIDE];
    const int tid = threadIdx.x;
    const int lane = tid & 31;
    const int gid = lane >> 2, tig = lane & 3;
    const int warp = tid >> 5;
    const int m0w = (warp >> 2) * 64, n0w = (warp & 3) * 32;
    const int h = blockIdx.z;
    const int iBase = blockIdx.y * 128, jBase = blockIdx.x * 128;
    const float* Qb = &g_qkv[0] + b * N_QKV + h * HD + (size_t)iBase * ROWSTRIDE;
    const float* Kb = &g_qkv[0] + b * N_QKV + E_DIM + h * HD + (size_t)jBase * ROWSTRIDE;

    float acc[4][4][4] = {};

    #pragma unroll
    for (int k0 = 0; k0 < HD; k0 += 32) {
        #pragma unroll
        for (int l = 0; l < 4; ++l) {
            stage_frag(Qb + k0, ROWSTRIDE, Qs, tid + l * 256);
            stage_frag(Kb + k0, ROWSTRIDE, Ks, tid + l * 256);
        }
        __syncthreads();
        warp_mma<4, SSTRIDE, SSTRIDE>(Qs, Ks, m0w, n0w, gid, tig, acc);
        __syncthreads();
    }

    float* S = &g_sc[0] + (size_t)h * T_DIM * T_DIM;
    #pragma unroll
    for (int mt = 0; mt < 4; ++mt) {
        int r0 = iBase + m0w + mt * 16 + gid;
        #pragma unroll
        for (int nt = 0; nt < 4; ++nt) {
            int c = jBase + n0w + nt * 8 + tig * 2;
            *reinterpret_cast<float2*>(S + (size_t)r0 * T_DIM + c) =
                make_float2(acc[mt][nt][0], acc[mt][nt][1]);
            *reinterpret_cast<float2*>(S + (size_t)(r0 + 8) * T_DIM + c) =
                make_float2(acc[mt][nt][2], acc[mt][nt][3]);
        }
    }
}

// ============================================================================
// Row stats + head-average for batch-group b. One block per row i.
// Reads RAW scores once; writes (max, 1/sum) to g_stats and the averaged
// probabilities to out_avg. Grid (2048).
// ============================================================================
__global__ __launch_bounds__(256) void rowstats_avg_kernel(int b, float* __restrict__ out_avg)
{
    __shared__ float sm[8];
    const int tid = threadIdx.x;
    const int i = blockIdx.x;

    float accum[8] = {};

    for (int h = 0; h < H_DIM; ++h) {
        const float* p = &g_sc[0] + ((size_t)h * T_DIM + i) * T_DIM;

        float r[8];
        #pragma unroll
        for (int j = 0; j < 8; ++j) r[j] = p[tid + j * 256];

        float m = r[0];
        #pragma unroll
        for (int j = 1; j < 8; ++j) m = fmaxf(m, r[j]);
        #pragma unroll
        for (int o = 16; o > 0; o >>= 1) m = fmaxf(m, __shfl_xor_sync(0xffffffffu, m, o));
        if ((tid & 31) == 0) sm[tid >> 5] = m;
        __syncthreads();
        m = sm[0];
        #pragma unroll
        for (int w = 1; w < 8; ++w) m = fmaxf(m, sm[w]);
        __syncthreads();

        float s = 0.f;
        #pragma unroll
        for (int j = 0; j < 8; ++j) { r[j] = __expf(r[j] - m); s += r[j]; }
        #pragma unroll
        for (int o = 16; o > 0; o >>= 1) s += __shfl_xor_sync(0xffffffffu, s, o);
        if ((tid & 31) == 0) sm[tid >> 5] = s;
        __syncthreads();
        s = 0.f;
        #pragma unroll
        for (int w = 0; w < 8; ++w) s += sm[w];

        float inv = 1.0f / s;
        if (tid == 0) g_stats[h * T_DIM + i] = make_float2(m, inv);
        #pragma unroll
        for (int j = 0; j < 8; ++j) accum[j] += r[j] * inv;
        __syncthreads();
    }

    float* q = out_avg + ((size_t)b * T_DIM + i) * T_DIM;
    #pragma unroll
    for (int j = 0; j < 8; ++j) q[tid + j * 256] = accum[j] * 0.125f;
}

// ============================================================================
// AV split-K for batch-group b: head h=blockIdx.y, split s=blockIdx.z covers
// k in [s*512, (s+1)*512). Partial C tile written to g_part[s] (compact
// [i, h*64+n] layout). Block 64m x 64n, 128 threads. Grid (32, 8, 4) = 1024
// blocks -> ~5 resident CTAs/SM (fixes R11's grid-limited occ=11%).
// ============================================================================
__global__ __launch_bounds__(128) void av_kernel(int b)
{
    __shared__ uint32_t Ps[32 * PSTRIDE];   // 8.7 KB  [k][row], 64 rows
    __shared__ uint32_t Vs[32 * PSTRIDE];   // 8.7 KB  [k][n],  64 cols
    __shared__ float2 sst[64];              // 0.5 KB

    const int tid = threadIdx.x;
    const int lane = tid & 31;
    const int gid = lane >> 2, tig = lane & 3;
    const int warp = tid >> 5;
    const int m0w = (warp >> 1) * 32, n0w = (warp & 1) * 32;
    const int h = blockIdx.y;
    const int s = blockIdx.z;
    const int iBase = blockIdx.x * 64;
    const int kBase = s * KSPLIT;
    const float* Pm = &g_sc[0] + (size_t)h * T_DIM * T_DIM + (size_t)iBase * T_DIM + kBase;
    const float* Vb = &g_qkv[0] + b * N_QKV + 2 * E_DIM + h * HD + (size_t)kBase * ROWSTRIDE;

    if (tid < 64) sst[tid] = g_stats[h * T_DIM + iBase + tid];
    __syncthreads();

    float acc[2][4][4] = {};
    float4 pv[4], vv[4];

    auto load_tiles = [&](int k0) {
        #pragma unroll
        for (int l = 0; l < 4; ++l) {
            int p = tid + l * 128;               // 64 rows x 8 float4-chunks
            int r = p >> 3, c4 = (p & 7) << 2;
            pv[l] = *reinterpret_cast<const float4*>(Pm + (size_t)r * T_DIM + k0 + c4);
        }
        #pragma unroll
        for (int l = 0; l < 4; ++l) {
            int p = tid + l * 128;               // 32 k x 16 float4-chunks
            int k = p >> 4, n4 = (p & 15) << 2;
            vv[l] = *reinterpret_cast<const float4*>(Vb + (size_t)(k0 + k) * ROWSTRIDE + n4);
        }
    };

    auto store_tiles = [&]() {
        #pragma unroll
        for (int l = 0; l < 4; ++l) {
            int p = tid + l * 128;
            int r = p >> 3, c4 = (p & 7) << 2;
            float2 st = sst[r];                  // x = rowmax, y = 1/rowsum
            float4 v = pv[l];
            Ps[(c4 + 0) * PSTRIDE + r] = f2tf(__expf(v.x - st.x) * st.y);
            Ps[(c4 + 1) * PSTRIDE + r] = f2tf(__expf(v.y - st.x) * st.y);
            Ps[(c4 + 2) * PSTRIDE + r] = f2tf(__expf(v.z - st.x) * st.y);
            Ps[(c4 + 3) * PSTRIDE + r] = f2tf(__expf(v.w - st.x) * st.y);
        }
        #pragma unroll
        for (int l = 0; l < 4; ++l) {
            int p = tid + l * 128;
            int k = p >> 4, n4 = (p & 15) << 2;
            float4 v = vv[l];
            Vs[k * PSTRIDE + n4 + 0] = f2tf(v.x);
            Vs[k * PSTRIDE + n4 + 1] = f2tf(v.y);
            Vs[k * PSTRIDE + n4 + 2] = f2tf(v.z);
            Vs[k * PSTRIDE + n4 + 3] = f2tf(v.w);
        }
    };

    load_tiles(0);
    store_tiles();
    __syncthreads();

    const int NT = KSPLIT / 32;   // 16 k-tiles per split
    for (int t = 0; t < NT; ++t) {
        if (t + 1 < NT) load_tiles((t + 1) * 32);   // LDGs in flight during mma
        warp_mma<2, PSTRIDE, PSTRIDE>(Ps, Vs, m0w, n0w, gid, tig, acc);
        __syncthreads();
        if (t + 1 < NT) {
            store_tiles();
            __syncthreads();
        }
    }

    float* P = &g_part[s][0];
    #pragma unroll
    for (int mt = 0; mt < 2; ++mt) {
        int i0 = iBase + m0w + mt * 16 + gid;
        #pragma unroll
        for (int nt = 0; nt < 4; ++nt) {
            int n = h * HD + n0w + nt * 8 + tig * 2;
            *reinterpret_cast<float2*>(&P[(size_t)i0 * E_DIM + n]) =
                make_float2(acc[mt][nt][0], acc[mt][nt][1]);
            *reinterpret_cast<float2*>(&P[(size_t)(i0 + 8) * E_DIM + n]) =
                make_float2(acc[mt][nt][2], acc[mt][nt][3]);
        }
    }
}

// ============================================================================
// Deterministic split-K reduce for batch-group b: g_attn = sum of 4 partials.
// Vectorized float4; fixed summation order. Grid (1024) x 256 threads.
// ============================================================================
__global__ __launch_bounds__(256) void reduce_kernel(int b)
{
    size_t idx = ((size_t)blockIdx.x * 256 + threadIdx.x) * 4;   // float index
    size_t i = idx >> 9;            // /512
    size_t c = idx & 511;
    float4 v0 = *reinterpret_cast<const float4*>(&g_part[0][idx]);
    float4 v1 = *reinterpret_cast<const float4*>(&g_part[1][idx]);
    float4 v2 = *reinterpret_cast<const float4*>(&g_part[2][idx]);
    float4 v3 = *reinterpret_cast<const float4*>(&g_part[3][idx]);
    float4 r;
    r.x = (v0.x + v1.x) + (v2.x + v3.x);
    r.y = (v0.y + v1.y) + (v2.y + v3.y);
    r.z = (v0.z + v1.z) + (v2.z + v3.z);
    r.w = (v0.w + v1.w) + (v2.w + v3.w);
    *reinterpret_cast<float4*>(&g_attn[(i * B_DIM + b) * E_DIM + c]) = r;
}

// ============================================================================
// Host launch — kernel launches only (graph-capturable)
// ============================================================================
extern "C" void kernel_launch(void* const* d_in, const int* in_sizes, int n_in,
                              void* d_out, int out_size)
{
    const float* x     = (const float*)d_in[0];  // [T,B,E]
    const float* w_in  = (const float*)d_in[1];  // [3E,E]
    const float* b_in  = (const float*)d_in[2];  // [3E]
    const float* w_out = (const float*)d_in[3];  // [E,E]
    const float* b_out = (const float*)d_in[4];  // [E]

    float* out_attn = (float*)d_out;                        // [T,B,E]
    float* out_avg  = out_attn + (size_t)M0 * E_DIM;        // [B,T,T]

    // 1) QKV projection (+bias, q scaled by HD^-0.5)
    qkv_kernel<<<dim3(N_QKV / 128, M0 / 128), 256>>>(x, w_in, b_in);

    // 2) per batch-group: raw scores -> row stats + avg -> split-K AV -> reduce
    for (int b = 0; b < B_DIM; ++b) {
        scores_kernel<<<dim3(T_DIM / 128, T_DIM / 128, H_DIM), 256>>>(b);
        rowstats_avg_kernel<<<dim3(T_DIM), 256>>>(b, out_avg);
        av_kernel<<<dim3(T_DIM / 64, H_DIM, NSPLIT), 128>>>(b);
        reduce_kernel<<<dim3((T_DIM * E_DIM) / (256 * 4)), 256>>>(b);
    }

    // 3) out projection (+bias) -> first output
    outproj_kernel<<<dim3(E_DIM / 128, M0 / 128), 256>>>(w_out, b_out, out_attn);
}